// round 8
// baseline (speedup 1.0000x reference)
#include <cuda_runtime.h>
#include <cuda_fp16.h>

#define NN 100000
#define NE 1000000

// ---------------------------------------------------------------------------
// Scratch
// P1h: fp16 table, one 128B row/node: halfs[0..39]=P1[o*4+k], halfs[40..49]=Q1[o]
// g_h1: root1 term per node, 16-float rows (cols 0..9 used)
// g_S : per node: attr-sum[0..3], deg(float) at [4] (8-float rows)
// slot*: edge data grouped by src (counting sort)
// ---------------------------------------------------------------------------
__device__ float4 g_P1h[(size_t)NN * 8];
__device__ float4 g_h1 [(size_t)NN * 4];
__device__ float4 g_S  [(size_t)NN * 2];
__device__ int    g_deg[NN];
__device__ int    g_base[NN + 1];
__device__ int    g_cursor[NN];
__device__ int    g_blockSum[256];
__device__ int    g_blockBase[256];
__device__ int    g_slotSrc[NE];
__device__ int    g_slotTgt[NE];
__device__ float4 g_slotAttr[NE];
__device__ float  g_red[64];  // v[i]=g_red[i] (i<10); T[i][k]=g_red[10+i*5+k]
__device__ int    g_is64;
__device__ unsigned int g_count;

// ---------------------------------------------------------------------------
__device__ __forceinline__ void load_edge(const void* ei, int ec, int e,
                                          int& src, int& tgt, int is64)
{
    if (is64) {
        const long long* p = (const long long*)ei;
        src = (int)__ldg(&p[e]);
        tgt = (int)__ldg(&p[(size_t)ec + e]);
    } else {
        const int* p = (const int*)ei;
        src = __ldg(&p[e]);
        tgt = __ldg(&p[(size_t)ec + e]);
    }
}

// ---------------------------------------------------------------------------
// k_zero: zero deg + g_red + count; dtype sniff (block 0).
// ---------------------------------------------------------------------------
__global__ void k_zero(const void* __restrict__ ei, int ec, int n)
{
    int tid = blockIdx.x * blockDim.x + threadIdx.x;
    for (int i = tid; i < n; i += gridDim.x * blockDim.x) g_deg[i] = 0;
    if (blockIdx.x == 0) {
        if (threadIdx.x < 64) g_red[threadIdx.x] = 0.f;
        if (threadIdx.x == 64) g_count = 0u;
        __shared__ int ok;
        if (threadIdx.x == 0) ok = 1;
        __syncthreads();
        const long long* p = (const long long*)ei;
        int m = ec < 128 ? ec : 128;
        if (threadIdx.x < m) {
            long long v = p[threadIdx.x];
            if (v < 0 || v >= n) ok = 0;
        }
        __syncthreads();
        if (threadIdx.x == 0) g_is64 = ok;
    }
}

// ---------------------------------------------------------------------------
// k_mid: block-role split.
//  node role: 128 nodes/block, 2 thr/node: root1 (f32) + P1h/Q1h (fp16).
//  edge role: deg[src]++ (single int RED).
// ---------------------------------------------------------------------------
__global__ void k_mid(const float* __restrict__ x,
                      const float* __restrict__ W1e, const float* __restrict__ b1e,
                      const float* __restrict__ Wr1, const float* __restrict__ bb1,
                      const void* __restrict__ ei, int n, int ec, int nodeBlocks)
{
    if (blockIdx.x >= nodeBlocks) {
        int e = (blockIdx.x - nodeBlocks) * blockDim.x + threadIdx.x;
        if (e >= ec) return;
        int src;
        if (g_is64) src = (int)__ldg(&((const long long*)ei)[e]);
        else        src = __ldg(&((const int*)ei)[e]);
        atomicAdd(&g_deg[src], 1);
        return;
    }

    __shared__ float sW[720], sB[180], sWr[180], sBB[16];
    __shared__ float sx[128 * 18];
    for (int i = threadIdx.x; i < 720; i += blockDim.x) sW[i] = W1e[i];
    for (int i = threadIdx.x; i < 180; i += blockDim.x) { sB[i] = b1e[i]; sWr[i] = Wr1[i]; }
    if (threadIdx.x < 10) sBB[threadIdx.x] = bb1[threadIdx.x];

    int nd0 = blockIdx.x * 128;
    int cnt = n - nd0; if (cnt > 128) cnt = 128;
    for (int i = threadIdx.x; i < cnt * 18; i += blockDim.x)
        sx[i] = __ldg(&x[(size_t)nd0 * 18 + i]);
    __syncthreads();

    int ndl  = threadIdx.x >> 1;
    int half = threadIdx.x & 1;
    if (ndl >= cnt) return;
    int nd = nd0 + ndl;

    float xv[18];
    #pragma unroll
    for (int i = 0; i < 18; i++) xv[i] = sx[ndl * 18 + i];

    __half2* prow = (__half2*)(g_P1h + (size_t)nd * 8);
    __half*  qrow = (__half*)prow;
    float*   hrow = (float*)(g_h1 + (size_t)nd * 4);

    int o0 = half * 5;
    #pragma unroll
    for (int oo = 0; oo < 5; oo++) {
        int o = o0 + oo;
        float p0 = 0.f, p1 = 0.f, p2 = 0.f, p3 = 0.f, q = 0.f, h = 0.f;
        #pragma unroll
        for (int i = 0; i < 18; i++) {
            int r = i * 10 + o;
            float xi = xv[i];
            p0 += xi * sW[r * 4 + 0];
            p1 += xi * sW[r * 4 + 1];
            p2 += xi * sW[r * 4 + 2];
            p3 += xi * sW[r * 4 + 3];
            q  += xi * sB[r];
            h  += xi * sWr[r];
        }
        prow[o * 2 + 0] = __floats2half2_rn(p0, p1);
        prow[o * 2 + 1] = __floats2half2_rn(p2, p3);
        qrow[40 + o]    = __float2half_rn(q);
        hrow[o]         = h + sBB[o];
    }
}

// ---------------------------------------------------------------------------
// Deterministic two-level exclusive scan of g_deg -> g_base, g_cursor.
// chunk = ceil(n/256) <= 512. 256 blocks of 512 threads.
// ---------------------------------------------------------------------------
__global__ void k_scanA(int n, int chunk)
{
    __shared__ int sv[512];
    int idx = blockIdx.x * chunk + threadIdx.x;
    int v = (threadIdx.x < chunk && idx < n) ? g_deg[idx] : 0;
    sv[threadIdx.x] = v;
    __syncthreads();
    for (int off = 256; off > 0; off >>= 1) {
        if (threadIdx.x < off) sv[threadIdx.x] += sv[threadIdx.x + off];
        __syncthreads();
    }
    if (threadIdx.x == 0) g_blockSum[blockIdx.x] = sv[0];
}

__global__ void k_scanB(int n, int ec)
{
    __shared__ int sv[256];
    int own = g_blockSum[threadIdx.x];
    sv[threadIdx.x] = own;
    __syncthreads();
    for (int d = 1; d < 256; d <<= 1) {
        int t = (threadIdx.x >= d) ? sv[threadIdx.x - d] : 0;
        __syncthreads();
        sv[threadIdx.x] += t;
        __syncthreads();
    }
    g_blockBase[threadIdx.x] = sv[threadIdx.x] - own;   // exclusive
    if (threadIdx.x == 0) g_base[n] = ec;               // sentinel
}

__global__ void k_scanC(int n, int chunk)
{
    __shared__ int sv[512];
    int idx = blockIdx.x * chunk + threadIdx.x;
    bool valid = (threadIdx.x < chunk && idx < n);
    int own = valid ? g_deg[idx] : 0;
    sv[threadIdx.x] = own;
    __syncthreads();
    for (int d = 1; d < 512; d <<= 1) {
        int t = (threadIdx.x >= d) ? sv[threadIdx.x - d] : 0;
        __syncthreads();
        sv[threadIdx.x] += t;
        __syncthreads();
    }
    if (valid) {
        int b = g_blockBase[blockIdx.x] + sv[threadIdx.x] - own;
        g_base[idx]   = b;
        g_cursor[idx] = b;
    }
}

// ---------------------------------------------------------------------------
// k_scatter: counting-sort edges into src-grouped slots.
// ---------------------------------------------------------------------------
__global__ void k_scatter(const void* __restrict__ ei,
                          const float4* __restrict__ attr, int ec)
{
    int e = blockIdx.x * blockDim.x + threadIdx.x;
    if (e >= ec) return;
    int src, tgt;
    load_edge(ei, ec, e, src, tgt, g_is64);
    float4 a = __ldg(&attr[e]);
    int pos = atomicAdd(&g_cursor[src], 1);
    g_slotSrc[pos]  = src;
    g_slotTgt[pos]  = tgt;
    g_slotAttr[pos] = a;
}

// ---------------------------------------------------------------------------
// k_snode: S[n] = (sum of own slotAttr segment, deg) — no atomics.
// ---------------------------------------------------------------------------
__global__ void k_snode(int n)
{
    int nd = blockIdx.x * blockDim.x + threadIdx.x;
    if (nd >= n) return;
    int b0 = g_base[nd], b1 = g_base[nd + 1];
    float4 s = make_float4(0.f, 0.f, 0.f, 0.f);
    for (int p = b0; p < b1; p++) {
        float4 a = __ldg(&g_slotAttr[p]);
        s.x += a.x; s.y += a.y; s.z += a.z; s.w += a.w;
    }
    float* sr = (float*)(g_S + (size_t)nd * 2);
    *(float4*)sr = s;
    sr[4] = (float)(b1 - b0);
}

// ---------------------------------------------------------------------------
// k_tail: root-stream + grouped-edge-stream (L1-friendly P gather),
// block reduce -> g_red, last block runs the MLP.
// ---------------------------------------------------------------------------
__global__ __launch_bounds__(256)
void k_tail(const float* __restrict__ Wr2, const float* __restrict__ bb2,
            const float* __restrict__ W2e, const float* __restrict__ b2e,
            const float* __restrict__ w1, const float* __restrict__ bw1,
            const float* __restrict__ w2, const float* __restrict__ bw2,
            const float* __restrict__ w3, const float* __restrict__ bw3,
            float* __restrict__ out, int n, int ec, int out_size)
{
    float v[10];
    float T[50];
    #pragma unroll
    for (int i = 0; i < 10; i++) v[i] = 0.f;
    #pragma unroll
    for (int i = 0; i < 50; i++) T[i] = 0.f;

    int stride = gridDim.x * blockDim.x;
    int g0 = blockIdx.x * blockDim.x + threadIdx.x;

    // root contribution (streaming)
    for (int nd = g0; nd < n; nd += stride) {
        const float* hr = (const float*)(g_h1 + (size_t)nd * 4);
        const float* sr = (const float*)(g_S  + (size_t)nd * 2);
        float4 ha = *(const float4*)hr;
        float4 hb = *(const float4*)(hr + 4);
        float2 hc = *(const float2*)(hr + 8);
        float hv[10] = {ha.x, ha.y, ha.z, ha.w, hb.x, hb.y, hb.z, hb.w, hc.x, hc.y};
        float4 s4 = *(const float4*)sr;
        float  sd = sr[4];
        #pragma unroll
        for (int i = 0; i < 10; i++) {
            float hi = hv[i];
            v[i] += hi;
            T[i * 5 + 0] += hi * s4.x;
            T[i * 5 + 1] += hi * s4.y;
            T[i * 5 + 2] += hi * s4.z;
            T[i * 5 + 3] += hi * s4.w;
            T[i * 5 + 4] += hi * sd;
        }
    }

    // message contribution over src-grouped slots (coalesced stream +
    // L1-shared P rows + random S[tgt] gather)
    for (int pos = g0; pos < ec; pos += stride) {
        int src  = __ldg(&g_slotSrc[pos]);
        int tgt  = __ldg(&g_slotTgt[pos]);
        float4 a = __ldg(&g_slotAttr[pos]);

        const float4* r = g_P1h + (size_t)src * 8;
        float4 raw[7];
        #pragma unroll
        for (int i = 0; i < 6; i++) raw[i] = __ldg(&r[i]);
        raw[6].x = __ldg((const float*)r + 24);
        const __half2* hp = (const __half2*)raw;

        float m[10];
        #pragma unroll
        for (int o = 0; o < 10; o++) {
            float2 pab = __half22float2(hp[o * 2 + 0]);
            float2 pcd = __half22float2(hp[o * 2 + 1]);
            m[o] = a.x * pab.x + a.y * pab.y + a.z * pcd.x + a.w * pcd.y;
        }
        #pragma unroll
        for (int j = 0; j < 5; j++) {
            float2 q2 = __half22float2(hp[20 + j]);
            m[j * 2 + 0] += q2.x;
            m[j * 2 + 1] += q2.y;
        }

        const float* sr = (const float*)(g_S + (size_t)tgt * 2);
        float4 s4 = __ldg((const float4*)sr);
        float  sd = __ldg(sr + 4);

        #pragma unroll
        for (int i = 0; i < 10; i++) {
            float mi = m[i];
            v[i] += mi;
            T[i * 5 + 0] += mi * s4.x;
            T[i * 5 + 1] += mi * s4.y;
            T[i * 5 + 2] += mi * s4.z;
            T[i * 5 + 3] += mi * s4.w;
            T[i * 5 + 4] += mi * sd;
        }
    }

    // block reduce -> g_red
    #pragma unroll
    for (int off = 16; off > 0; off >>= 1) {
        #pragma unroll
        for (int i = 0; i < 10; i++) v[i] += __shfl_down_sync(0xffffffffu, v[i], off);
        #pragma unroll
        for (int i = 0; i < 50; i++) T[i] += __shfl_down_sync(0xffffffffu, T[i], off);
    }
    __shared__ float sh[8][64];
    int w = threadIdx.x >> 5, l = threadIdx.x & 31;
    if (l == 0) {
        #pragma unroll
        for (int i = 0; i < 10; i++) sh[w][i] = v[i];
        #pragma unroll
        for (int i = 0; i < 50; i++) sh[w][10 + i] = T[i];
    }
    __syncthreads();
    if (threadIdx.x < 60) {
        float t = 0.f;
        #pragma unroll
        for (int ww = 0; ww < 8; ww++) t += sh[ww][threadIdx.x];
        atomicAdd(&g_red[threadIdx.x], t);
    }
    __threadfence();
    __syncthreads();

    __shared__ int isLast;
    if (threadIdx.x == 0) {
        unsigned int prev = atomicAdd(&g_count, 1u);
        isLast = (prev == gridDim.x - 1) ? 1 : 0;
    }
    __syncthreads();
    if (!isLast) return;

    volatile float* gr = g_red;
    __shared__ float g[8];
    int lane = threadIdx.x;
    float invn = 1.0f / (float)n;
    if (lane < 7) {
        int o = lane;
        float s = (float)n * bb2[o];
        #pragma unroll
        for (int i = 0; i < 10; i++) {
            float vi = gr[i];
            s += vi * Wr2[i * 7 + o];
            int rr = i * 7 + o;
            #pragma unroll
            for (int k = 0; k < 4; k++) s += gr[10 + i * 5 + k] * W2e[rr * 4 + k];
            s += gr[10 + i * 5 + 4] * b2e[rr];
        }
        g[o] = s * invn;
    }
    __syncthreads();
    if (lane == 0) {
        float gg[7];
        #pragma unroll
        for (int k = 0; k < 7; k++) gg[k] = g[k];
        float g1[20];
        for (int j = 0; j < 20; j++) {
            float val = bw1[j];
            #pragma unroll
            for (int k = 0; k < 7; k++) val += gg[k] * w1[j * 7 + k];
            g1[j] = val > 0.f ? val : 0.f;
        }
        float g2[10];
        for (int j = 0; j < 10; j++) {
            float val = bw2[j];
            #pragma unroll
            for (int k = 0; k < 20; k++) val += g1[k] * w2[j * 20 + k];
            g2[j] = val > 0.f ? val : 0.f;
        }
        float z = bw3[0];
        #pragma unroll
        for (int k = 0; k < 10; k++) z += g2[k] * w3[k];
        float r = 1.0f / (1.0f + expf(-z));
        for (int i = 0; i < out_size; i++) out[i] = r;
    }
}

// ---------------------------------------------------------------------------
extern "C" void kernel_launch(void* const* d_in, const int* in_sizes, int n_in,
                              void* d_out, int out_size)
{
    const float*  x    = (const float*)d_in[0];
    const void*   ei   = d_in[1];
    const float4* attr = (const float4*)d_in[2];
    const float* W1e = (const float*)d_in[3];
    const float* b1e = (const float*)d_in[4];
    const float* Wr1 = (const float*)d_in[5];
    const float* bb1 = (const float*)d_in[6];
    const float* W2e = (const float*)d_in[7];
    const float* b2e = (const float*)d_in[8];
    const float* Wr2 = (const float*)d_in[9];
    const float* bb2 = (const float*)d_in[10];
    const float* w1  = (const float*)d_in[11];
    const float* bw1 = (const float*)d_in[12];
    const float* w2  = (const float*)d_in[13];
    const float* bw2 = (const float*)d_in[14];
    const float* w3  = (const float*)d_in[15];
    const float* bw3 = (const float*)d_in[16];

    int n = in_sizes[0] / 18;
    int e = in_sizes[2] / 4;
    if (n > NN) n = NN;
    if (e > NE) e = NE;

    const int T = 256;
    int nodeBlocks = (n + 127) / 128;
    int edgeBlocks = (e + T - 1) / T;
    int chunk = (n + 255) / 256;            // <= 512 for n <= 100000

    k_zero<<<128, T>>>(ei, e, n);
    k_mid<<<nodeBlocks + edgeBlocks, T>>>(x, W1e, b1e, Wr1, bb1, ei, n, e, nodeBlocks);
    k_scanA<<<256, 512>>>(n, chunk);
    k_scanB<<<1, 256>>>(n, e);
    k_scanC<<<256, 512>>>(n, chunk);
    k_scatter<<<edgeBlocks, T>>>(ei, attr, e);
    k_snode<<<(n + T - 1) / T, T>>>(n);
    k_tail<<<296, T>>>(Wr2, bb2, W2e, b2e, w1, bw1, w2, bw2, w3, bw3,
                       (float*)d_out, n, e, out_size);
}